// round 5
// baseline (speedup 1.0000x reference)
#include <cuda_runtime.h>
#include <cuda_bf16.h>
#include <math_constants.h>

// Problem constants
#define TLEN   1024
#define SLEN   1024
#define BSZ    16
#define EMB    256
#define NH     8
#define HD     32
#define BH     (BSZ*NH)        // 128
#define MROWS  (TLEN*BSZ)      // 16384
#define QSCALE 0.17677669529663688f   // 1/sqrt(32)

typedef unsigned long long u64;

// ---- packed fp32x2 helpers (Blackwell FFMA2 path) --------------------------
__device__ __forceinline__ u64 pk2(float x, float y) {
    u64 r; asm("mov.b64 %0, {%1,%2};" : "=l"(r) : "f"(x), "f"(y)); return r;
}
__device__ __forceinline__ void fma2(u64& d, u64 a, u64 b) {
    asm("fma.rn.f32x2 %0, %1, %2, %0;" : "+l"(d) : "l"(a), "l"(b));
}
__device__ __forceinline__ float2 up2(u64 v) {
    float2 r; asm("mov.b64 {%0,%1}, %2;" : "=f"(r.x), "=f"(r.y) : "l"(v)); return r;
}
__device__ __forceinline__ void pbar(int id) {
    asm volatile("bar.sync %0, 64;" :: "r"(id) : "memory");
}

// ---------------- scratch (device globals; no allocation allowed) ----------
__device__ float g_Q[(size_t)BH*SLEN*HD];   // scaled by 1/sqrt(hd)
__device__ float g_K[(size_t)BH*SLEN*HD];
__device__ float g_V[(size_t)BH*SLEN*HD];
__device__ float g_ctx[(size_t)MROWS*EMB];  // [t][b][h*32+d]

// ---------------- zero kernel ----------------------------------------------
__global__ void zero_f4(float4* __restrict__ p, int n4) {
    int i = blockIdx.x * blockDim.x + threadIdx.x;
    int stride = gridDim.x * blockDim.x;
    float4 z = make_float4(0.f, 0.f, 0.f, 0.f);
    for (; i < n4; i += stride) p[i] = z;
}

// ---------------- fp32 tiled GEMM (f32x2 inner):  out = X.W^T + b -----------
#define XS_STR 132
#define WS_STR 68

template<int MODE>
__global__ __launch_bounds__(256)
void gemm_k(const float* __restrict__ Xq, const float* __restrict__ Xk,
            const float* __restrict__ Xv, const float* __restrict__ W,
            const float* __restrict__ bias, float* __restrict__ outp)
{
    __shared__ float Xs[16 * XS_STR];
    __shared__ float Ws[16 * WS_STR];

    const int n0 = blockIdx.x * 64;
    const int m0 = blockIdx.y * 128;
    const int tid = threadIdx.x;
    const int tx = tid & 15;
    const int ty = tid >> 4;

    const float* X;
    if (MODE == 0) {
        int sec = n0 >> 8;
        X = (sec == 0) ? Xq : (sec == 1 ? Xk : Xv);
    } else {
        X = g_ctx;
    }

    u64 acc2[16];
#pragma unroll
    for (int i = 0; i < 16; i++) acc2[i] = 0ull;

    for (int kc = 0; kc < 16; kc++) {
        const int k0 = kc * 16;
#pragma unroll
        for (int l = 0; l < 2; l++) {
            int id = tid + l * 256;
            int r  = id >> 2;
            int kq = (id & 3) * 4;
            float4 xv = *reinterpret_cast<const float4*>(X + (size_t)(m0 + r) * 256 + k0 + kq);
            Xs[(kq + 0) * XS_STR + r] = xv.x;
            Xs[(kq + 1) * XS_STR + r] = xv.y;
            Xs[(kq + 2) * XS_STR + r] = xv.z;
            Xs[(kq + 3) * XS_STR + r] = xv.w;
        }
        {
            int n  = tid >> 2;
            int kq = (tid & 3) * 4;
            float4 wv = *reinterpret_cast<const float4*>(W + (size_t)(n0 + n) * 256 + k0 + kq);
            Ws[(kq + 0) * WS_STR + n] = wv.x;
            Ws[(kq + 1) * WS_STR + n] = wv.y;
            Ws[(kq + 2) * WS_STR + n] = wv.z;
            Ws[(kq + 3) * WS_STR + n] = wv.w;
        }
        __syncthreads();

#pragma unroll
        for (int kk = 0; kk < 16; kk++) {
            float4 a0 = *reinterpret_cast<const float4*>(&Xs[kk * XS_STR + ty * 8]);
            float4 a1 = *reinterpret_cast<const float4*>(&Xs[kk * XS_STR + ty * 8 + 4]);
            float4 b0 = *reinterpret_cast<const float4*>(&Ws[kk * WS_STR + tx * 4]);
            u64 am[4];
            am[0] = pk2(a0.x, a0.y); am[1] = pk2(a0.z, a0.w);
            am[2] = pk2(a1.x, a1.y); am[3] = pk2(a1.z, a1.w);
            u64 bb[4];
            bb[0] = pk2(b0.x, b0.x); bb[1] = pk2(b0.y, b0.y);
            bb[2] = pk2(b0.z, b0.z); bb[3] = pk2(b0.w, b0.w);
#pragma unroll
            for (int p = 0; p < 4; p++)
#pragma unroll
                for (int jn = 0; jn < 4; jn++)
                    fma2(acc2[p * 4 + jn], am[p], bb[jn]);
        }
        __syncthreads();
    }

#pragma unroll
    for (int p = 0; p < 4; p++) {
#pragma unroll
        for (int jn = 0; jn < 4; jn++) {
            float2 v2 = up2(acc2[p * 4 + jn]);
            int ng = n0 + tx * 4 + jn;
            float bv = bias[ng];
#pragma unroll
            for (int half = 0; half < 2; half++) {
                int r = m0 + ty * 8 + 2 * p + half;
                float v = (half ? v2.y : v2.x) + bv;
                if (MODE == 0) {
                    int sec = ng >> 8;
                    int nl  = ng & 255;
                    int h   = nl >> 5;
                    int d   = nl & 31;
                    int t   = r >> 4;
                    int b   = r & 15;
                    size_t idx = (((size_t)(b * 8 + h)) * SLEN + t) * HD + d;
                    if (sec == 0)      g_Q[idx] = v * QSCALE;
                    else if (sec == 1) g_K[idx] = v;
                    else               g_V[idx] = v;
                } else {
                    outp[(size_t)r * 256 + ng] = v;
                }
            }
        }
    }
}

// ---------------- fused attention (warp-pair s-split, R=4 K-reuse) ----------
// 128 blocks (one per bh), 512 threads = 16 warps = 8 pairs.
// Pair p handles rows [p*128,(p+1)*128) in 32 groups of 4 rows.
// Within a pair, warp hw owns s-range [hw*512, hw*512+512).
// smem: K^T [32][1024] fp32 (128KB) + reduction buffers (~9KB).
__global__ __launch_bounds__(512, 1)
void attn_kernel(float* __restrict__ attnw /* [16,1024,1024] */)
{
    extern __shared__ float sK[];            // sK[d*1024 + s], 32768 floats
    float* red_s = sK + 32 * 1024;           // [pair][parity][hw][4]  = 128
    float* red_c = red_s + 128;              // [pair][parity][hw][4]  = 128
    float* obuf  = red_c + 128;              // [pair][hw][4][32]      = 2048

    const int bh   = blockIdx.x;
    const int tid  = threadIdx.x;
    const int lane = tid & 31;
    const int wid  = tid >> 5;      // 0..15
    const int pair = wid >> 1;      // 0..7
    const int hw   = wid & 1;       // s-half
    const int bid  = 1 + pair;      // named barrier id
    const int b    = bh >> 3;
    const int h    = bh & 7;
    const int sbase = hw * 512;

    // ---- load K[bh] transposed into smem ----
    const float* Kg = g_K + (size_t)bh * (SLEN * HD);
    for (int e4 = tid; e4 < (SLEN * HD) / 4; e4 += 512) {
        float4 v = reinterpret_cast<const float4*>(Kg)[e4];
        int s  = e4 >> 3;
        int dq = (e4 & 7) * 4;
        sK[(dq + 0) * SLEN + s] = v.x;
        sK[(dq + 1) * SLEN + s] = v.y;
        sK[(dq + 2) * SLEN + s] = v.z;
        sK[(dq + 3) * SLEN + s] = v.w;
    }
    __syncthreads();

    const float* Vg = g_V + (size_t)bh * (SLEN * HD);
    const float* Qg = g_Q + (size_t)bh * (SLEN * HD);

    for (int blk = 0; blk < 32; blk++) {
        const int t0 = pair * 128 + blk * 4;

        float qv[4];
#pragma unroll
        for (int r = 0; r < 4; r++) qv[r] = Qg[(size_t)(t0 + r) * HD + lane];

        // acc[r][2c+half]: packed score pair; lane owns s = sbase + c*128 + lane*4 + q
        u64 acc[4][8];
#pragma unroll
        for (int r = 0; r < 4; r++)
#pragma unroll
            for (int j = 0; j < 8; j++) acc[r][j] = 0ull;

#pragma unroll 4
        for (int d = 0; d < 32; d++) {
            u64 qq[4];
#pragma unroll
            for (int r = 0; r < 4; r++) {
                float qd = __shfl_sync(0xffffffffu, qv[r], d);
                qq[r] = pk2(qd, qd);
            }
            const ulonglong2* kp =
                reinterpret_cast<const ulonglong2*>(sK + d * SLEN + sbase) + lane;
#pragma unroll
            for (int c = 0; c < 4; c++) {
                ulonglong2 k4 = kp[c * 32];
#pragma unroll
                for (int r = 0; r < 4; r++) {
                    fma2(acc[r][2 * c + 0], qq[r], k4.x);
                    fma2(acc[r][2 * c + 1], qq[r], k4.y);
                }
            }
        }

        // unpack (register-pair reinterpret; near-free)
        float2 af[4][8];
#pragma unroll
        for (int r = 0; r < 4; r++)
#pragma unroll
            for (int j = 0; j < 8; j++) af[r][j] = up2(acc[r][j]);

        // ---- distributed sparsemax (Michelot) over the warp pair ----
        float tau[4], prevc[4];
        int par = 0;
        {
            float ls[4];
#pragma unroll
            for (int r = 0; r < 4; r++) {
                float s = 0.f;
#pragma unroll
                for (int j = 0; j < 8; j++) s += af[r][j].x + af[r][j].y;
#pragma unroll
                for (int o = 16; o > 0; o >>= 1) s += __shfl_xor_sync(0xffffffffu, s, o);
                ls[r] = s;
            }
            if (lane == 0) {
                int base = ((pair * 2 + par) * 2 + hw) * 4;
#pragma unroll
                for (int r = 0; r < 4; r++) red_s[base + r] = ls[r];
            }
            pbar(bid);
            int b0 = ((pair * 2 + par) * 2 + 0) * 4;
            int b1 = ((pair * 2 + par) * 2 + 1) * 4;
#pragma unroll
            for (int r = 0; r < 4; r++) {
                float tot = red_s[b0 + r] + red_s[b1 + r];
                tau[r] = (tot - 1.0f) * (1.0f / 1024.0f);
                prevc[r] = 1024.0f;
            }
            par ^= 1;
        }

        for (int iter = 0; iter < 64; iter++) {
            float lsum[4], lcnt[4];
#pragma unroll
            for (int r = 0; r < 4; r++) {
                float s = 0.f, c = 0.f;
#pragma unroll
                for (int j = 0; j < 8; j++) {
                    if (af[r][j].x > tau[r]) { s += af[r][j].x; c += 1.f; }
                    if (af[r][j].y > tau[r]) { s += af[r][j].y; c += 1.f; }
                }
#pragma unroll
                for (int o = 16; o > 0; o >>= 1) {
                    s += __shfl_xor_sync(0xffffffffu, s, o);
                    c += __shfl_xor_sync(0xffffffffu, c, o);
                }
                lsum[r] = s; lcnt[r] = c;
            }
            if (lane == 0) {
                int base = ((pair * 2 + par) * 2 + hw) * 4;
#pragma unroll
                for (int r = 0; r < 4; r++) { red_s[base + r] = lsum[r]; red_c[base + r] = lcnt[r]; }
            }
            pbar(bid);
            int b0 = ((pair * 2 + par) * 2 + 0) * 4;
            int b1 = ((pair * 2 + par) * 2 + 1) * 4;
            bool all = true;
#pragma unroll
            for (int r = 0; r < 4; r++) {
                float S = red_s[b0 + r] + red_s[b1 + r];
                float C = red_c[b0 + r] + red_c[b1 + r];
                if (C != prevc[r]) {
                    tau[r] = (S - 1.0f) / C;
                    prevc[r] = C;
                    all = false;
                }
            }
            par ^= 1;
            if (all) break;
        }

        // ---- AV (sparse, per warp s-half) + averaged attn weights ----
#pragma unroll 1
        for (int r = 0; r < 4; r++) {
            const int t = t0 + r;
            float* awrow = attnw + ((size_t)b * TLEN + t) * SLEN;
            float outv = 0.f;
#pragma unroll
            for (int i = 0; i < 16; i++) {
                float v = (i & 1) ? af[r][i >> 1].y : af[r][i >> 1].x;
                bool act = v > tau[r];
                float w = act ? (v - tau[r]) : 0.f;
                unsigned m = __ballot_sync(0xffffffffu, act);
                if (act) {
                    int s_me = sbase + (i >> 2) * 128 + lane * 4 + (i & 3);
                    atomicAdd(awrow + s_me, 0.125f * w);
                }
                while (m) {
                    int j = __ffs(m) - 1;
                    m &= m - 1;
                    float wj = __shfl_sync(0xffffffffu, w, j);
                    int s = sbase + (i >> 2) * 128 + j * 4 + (i & 3);
                    outv = fmaf(wj, Vg[(size_t)s * HD + lane], outv);
                }
            }
            obuf[((pair * 2 + hw) * 4 + r) * 32 + lane] = outv;
        }
        pbar(bid);
#pragma unroll
        for (int rr = 0; rr < 2; rr++) {
            int r = hw * 2 + rr;
            int t = t0 + r;
            float o = obuf[((pair * 2 + 0) * 4 + r) * 32 + lane]
                    + obuf[((pair * 2 + 1) * 4 + r) * 32 + lane];
            g_ctx[((size_t)t * BSZ + b) * EMB + h * HD + lane] = o;
        }
        // no trailing barrier needed: next group's first pbar (sparsemax init)
        // orders obuf reads before any reuse.
    }
}

// ---------------- launcher ---------------------------------------------------
extern "C" void kernel_launch(void* const* d_in, const int* in_sizes, int n_in,
                              void* d_out, int out_size)
{
    const float* query = (const float*)d_in[0];
    const float* key   = (const float*)d_in[1];
    const float* value = (const float*)d_in[2];
    const float* Win   = (const float*)d_in[3];
    const float* bin   = (const float*)d_in[4];
    const float* Wout  = (const float*)d_in[5];
    const float* bout  = (const float*)d_in[6];

    float* outp  = (float*)d_out;                         // [1024,16,256]
    float* attnw = outp + (size_t)MROWS * EMB;            // [16,1024,1024]

    const int ATTN_SMEM = (32 * 1024 + 2304) * (int)sizeof(float);
    cudaFuncSetAttribute(attn_kernel, cudaFuncAttributeMaxDynamicSharedMemorySize,
                         ATTN_SMEM);

    // 1) zero averaged attention-weights output (sparse atomics accumulate into it)
    zero_f4<<<2048, 256>>>((float4*)attnw, (int)((size_t)BSZ * TLEN * SLEN / 4));

    // 2) QKV projection (M=16384, N=768, K=256)
    gemm_k<0><<<dim3(768 / 64, MROWS / 128), 256>>>(query, key, value, Win, bin, nullptr);

    // 3) fused attention: scores + sparsemax + AV + avg attn weights
    attn_kernel<<<BH, 512, ATTN_SMEM>>>(attnw);

    // 4) output projection (M=16384, N=256, K=256)
    gemm_k<1><<<dim3(256 / 64, MROWS / 128), 256>>>(nullptr, nullptr, nullptr, Wout, bout, outp);
}

// round 6
// speedup vs baseline: 1.3423x; 1.3423x over previous
#include <cuda_runtime.h>
#include <cuda_bf16.h>
#include <math_constants.h>

// Problem constants
#define TLEN   1024
#define SLEN   1024
#define BSZ    16
#define EMB    256
#define NH     8
#define HD     32
#define BH     (BSZ*NH)        // 128
#define MROWS  (TLEN*BSZ)      // 16384
#define QSCALE 0.17677669529663688f   // 1/sqrt(32)

typedef unsigned long long u64;

// ---- packed fp32x2 helpers --------------------------------------------------
__device__ __forceinline__ u64 pk2(float x, float y) {
    u64 r; asm("mov.b64 %0, {%1,%2};" : "=l"(r) : "f"(x), "f"(y)); return r;
}
__device__ __forceinline__ void fma2(u64& d, u64 a, u64 b) {
    asm("fma.rn.f32x2 %0, %1, %2, %0;" : "+l"(d) : "l"(a), "l"(b));
}
__device__ __forceinline__ float2 up2(u64 v) {
    float2 r; asm("mov.b64 {%0,%1}, %2;" : "=f"(r.x), "=f"(r.y) : "l"(v)); return r;
}

// ---------------- scratch (device globals; no allocation allowed) ----------
__device__ float g_QKV[(size_t)MROWS * 768];   // [t*16+b][sec*256 + h*32 + d], q pre-scaled
__device__ float g_ctx[(size_t)MROWS * EMB];   // [t*16+b][h*32+d]

// ---------------- zero kernel ----------------------------------------------
__global__ void zero_f4(float4* __restrict__ p, int n4) {
    int i = blockIdx.x * blockDim.x + threadIdx.x;
    int stride = gridDim.x * blockDim.x;
    float4 z = make_float4(0.f, 0.f, 0.f, 0.f);
    for (; i < n4; i += stride) p[i] = z;
}

// ---------------- fp32 tiled GEMM (f32x2, reg-prefetch):  out = X.W^T + b ---
// M=16384, K=256.  BM=128, BN=64, BK=16, 256 threads, 8x4 micro tile.
// MODE 0: out -> g_QKV (q section scaled), X chosen per n-section
// MODE 1: X = g_ctx, out -> outp [r*256+n]
#define XS_STR 132
#define WS_STR 68

template<int MODE>
__global__ __launch_bounds__(256)
void gemm_k(const float* __restrict__ Xq, const float* __restrict__ Xk,
            const float* __restrict__ Xv, const float* __restrict__ W,
            const float* __restrict__ bias, float* __restrict__ outp)
{
    __shared__ float Xs[16 * XS_STR];
    __shared__ float Ws[16 * WS_STR];

    const int n0 = blockIdx.x * 64;
    const int m0 = blockIdx.y * 128;
    const int tid = threadIdx.x;
    const int tx = tid & 15;
    const int ty = tid >> 4;

    const float* X;
    if (MODE == 0) {
        int sec = n0 >> 8;
        X = (sec == 0) ? Xq : (sec == 1 ? Xk : Xv);
    } else {
        X = g_ctx;
    }

    // per-thread load coordinates
    const int xr0 = tid >> 2;            // X row for l=0
    const int xkq = (tid & 3) * 4;       // X k offset
    const int wn  = tid >> 2;            // W row
    // prefetch registers
    float4 xv0, xv1, wv;
    {
        xv0 = *reinterpret_cast<const float4*>(X + (size_t)(m0 + xr0) * 256 + xkq);
        xv1 = *reinterpret_cast<const float4*>(X + (size_t)(m0 + xr0 + 64) * 256 + xkq);
        wv  = *reinterpret_cast<const float4*>(W + (size_t)(n0 + wn) * 256 + xkq);
    }

    u64 acc2[16];
#pragma unroll
    for (int i = 0; i < 16; i++) acc2[i] = 0ull;

    for (int kc = 0; kc < 16; kc++) {
        // store prefetched tile to smem
        Xs[(xkq + 0) * XS_STR + xr0] = xv0.x;
        Xs[(xkq + 1) * XS_STR + xr0] = xv0.y;
        Xs[(xkq + 2) * XS_STR + xr0] = xv0.z;
        Xs[(xkq + 3) * XS_STR + xr0] = xv0.w;
        Xs[(xkq + 0) * XS_STR + xr0 + 64] = xv1.x;
        Xs[(xkq + 1) * XS_STR + xr0 + 64] = xv1.y;
        Xs[(xkq + 2) * XS_STR + xr0 + 64] = xv1.z;
        Xs[(xkq + 3) * XS_STR + xr0 + 64] = xv1.w;
        Ws[(xkq + 0) * WS_STR + wn] = wv.x;
        Ws[(xkq + 1) * WS_STR + wn] = wv.y;
        Ws[(xkq + 2) * WS_STR + wn] = wv.z;
        Ws[(xkq + 3) * WS_STR + wn] = wv.w;
        __syncthreads();

        // prefetch next k-chunk while computing
        if (kc < 15) {
            const int k0n = (kc + 1) * 16 + xkq;
            xv0 = *reinterpret_cast<const float4*>(X + (size_t)(m0 + xr0) * 256 + k0n);
            xv1 = *reinterpret_cast<const float4*>(X + (size_t)(m0 + xr0 + 64) * 256 + k0n);
            wv  = *reinterpret_cast<const float4*>(W + (size_t)(n0 + wn) * 256 + k0n);
        }

#pragma unroll
        for (int kk = 0; kk < 16; kk++) {
            // am pairs read directly as u64 (consecutive m in smem)
            const u64* ap = reinterpret_cast<const u64*>(&Xs[kk * XS_STR + ty * 8]);
            u64 am0 = ap[0], am1 = ap[1], am2 = ap[2], am3 = ap[3];
            float4 b0 = *reinterpret_cast<const float4*>(&Ws[kk * WS_STR + tx * 4]);
            u64 bb0 = pk2(b0.x, b0.x), bb1 = pk2(b0.y, b0.y);
            u64 bb2 = pk2(b0.z, b0.z), bb3 = pk2(b0.w, b0.w);
            fma2(acc2[ 0], am0, bb0); fma2(acc2[ 1], am0, bb1);
            fma2(acc2[ 2], am0, bb2); fma2(acc2[ 3], am0, bb3);
            fma2(acc2[ 4], am1, bb0); fma2(acc2[ 5], am1, bb1);
            fma2(acc2[ 6], am1, bb2); fma2(acc2[ 7], am1, bb3);
            fma2(acc2[ 8], am2, bb0); fma2(acc2[ 9], am2, bb1);
            fma2(acc2[10], am2, bb2); fma2(acc2[11], am2, bb3);
            fma2(acc2[12], am3, bb0); fma2(acc2[13], am3, bb1);
            fma2(acc2[14], am3, bb2); fma2(acc2[15], am3, bb3);
        }
        __syncthreads();
    }

    // epilogue (coalesced-ish; natural row-major layouts for both modes)
#pragma unroll
    for (int p = 0; p < 4; p++) {
#pragma unroll
        for (int jn = 0; jn < 4; jn++) {
            float2 v2 = up2(acc2[p * 4 + jn]);
            int ng = n0 + tx * 4 + jn;
            float bv = bias[ng];
#pragma unroll
            for (int half = 0; half < 2; half++) {
                int r = m0 + ty * 8 + 2 * p + half;
                float v = (half ? v2.y : v2.x) + bv;
                if (MODE == 0) {
                    if (ng < 256) v *= QSCALE;
                    g_QKV[(size_t)r * 768 + ng] = v;
                } else {
                    outp[(size_t)r * 256 + ng] = v;
                }
            }
        }
    }
}

// ---------------- fused attention: scores + sparsemax + AV + avg weights ----
// 128 blocks (one per bh), 512 threads (16 warps), warp owns full rows (R=2).
// sK layout XOR-swizzled: element K[s][d] at  d*1024 + (((s>>2)^(d>>2))<<2) + (s&3)
//  -> conflict-free transpose stores AND conflict-free score reads.
__global__ __launch_bounds__(512, 1)
void attn_kernel(float* __restrict__ attnw /* [16,1024,1024] */)
{
    extern __shared__ float sK[];   // 32*1024 floats
    const int bh   = blockIdx.x;
    const int tid  = threadIdx.x;
    const int lane = tid & 31;
    const int wid  = tid >> 5;      // 0..15
    const int b    = bh >> 3;
    const int h    = bh & 7;

    const float* QKV = g_QKV;
    const int qoff = h * 32;
    const int koff = 256 + h * 32;
    const int voff = 512 + h * 32;

    // ---- load K[bh] into swizzled-transposed smem (conflict-free) ----
    for (int e4 = tid; e4 < (SLEN * HD) / 4; e4 += 512) {
        int s  = e4 >> 3;
        int dq = (e4 & 7) * 4;
        float4 v = *reinterpret_cast<const float4*>(
            QKV + ((size_t)s * 16 + b) * 768 + koff + dq);
        int g = s >> 2;
        int sj = s & 3;
        sK[(dq + 0) * 1024 + ((g ^ ((dq + 0) >> 2)) << 2) + sj] = v.x;
        sK[(dq + 1) * 1024 + ((g ^ ((dq + 1) >> 2)) << 2) + sj] = v.y;
        sK[(dq + 2) * 1024 + ((g ^ ((dq + 2) >> 2)) << 2) + sj] = v.z;
        sK[(dq + 3) * 1024 + ((g ^ ((dq + 3) >> 2)) << 2) + sj] = v.w;
    }
    __syncthreads();

    for (int blk0 = 0; blk0 < 32; blk0++) {
        const int blk = (blk0 + wid * 2) & 31;   // stagger warps' phases
        const int t0 = wid * 64 + blk * 2;

        float qv0 = QKV[((size_t)(t0 + 0) * 16 + b) * 768 + qoff + lane];
        float qv1 = QKV[((size_t)(t0 + 1) * 16 + b) * 768 + qoff + lane];

        // acc2[r][2c+half]: packed score pair, s = c*128 + lane*4 + (2*half..+1)
        u64 acc2[2][16];
#pragma unroll
        for (int r = 0; r < 2; r++)
#pragma unroll
            for (int j = 0; j < 16; j++) acc2[r][j] = 0ull;

#pragma unroll 4
        for (int d = 0; d < 32; d++) {
            float q0 = __shfl_sync(0xffffffffu, qv0, d);
            float q1 = __shfl_sync(0xffffffffu, qv1, d);
            u64 qq0 = pk2(q0, q0);
            u64 qq1 = pk2(q1, q1);
            const float* basep = sK + d * 1024 + ((lane ^ (d >> 2)) << 2);
#pragma unroll
            for (int c = 0; c < 8; c++) {
                ulonglong2 k4 = *reinterpret_cast<const ulonglong2*>(basep + c * 128);
                fma2(acc2[0][2 * c + 0], qq0, k4.x);
                fma2(acc2[0][2 * c + 1], qq0, k4.y);
                fma2(acc2[1][2 * c + 0], qq1, k4.x);
                fma2(acc2[1][2 * c + 1], qq1, k4.y);
            }
        }

        // ---- per-row sparsemax + AV + averaged attention weights ----
#pragma unroll 1
        for (int r = 0; r < 2; r++) {
            float a[32];
#pragma unroll
            for (int c = 0; c < 8; c++) {
                float2 p0 = up2(acc2[r][2 * c + 0]);
                float2 p1 = up2(acc2[r][2 * c + 1]);
                a[4 * c + 0] = p0.x; a[4 * c + 1] = p0.y;
                a[4 * c + 2] = p1.x; a[4 * c + 3] = p1.y;
            }

            // Michelot starting from tau = max(z) - 1 (valid superset of support)
            float mx = a[0];
#pragma unroll
            for (int i = 1; i < 32; i++) mx = fmaxf(mx, a[i]);
#pragma unroll
            for (int o = 16; o > 0; o >>= 1)
                mx = fmaxf(mx, __shfl_xor_sync(0xffffffffu, mx, o));
            float tau = mx - 1.0f;
            int prevc = -1;

            for (int iter = 0; iter < 64; iter++) {
                float s = 0.f;
                int   c = 0;
#pragma unroll
                for (int i = 0; i < 32; i++) {
                    if (a[i] > tau) { s += a[i]; c++; }
                }
#pragma unroll
                for (int o = 16; o > 0; o >>= 1) {
                    s += __shfl_xor_sync(0xffffffffu, s, o);
                    c += __shfl_xor_sync(0xffffffffu, c, o);
                }
                if (c == prevc) break;
                tau = (s - 1.0f) / (float)c;
                prevc = c;
            }

            const int t = t0 + r;
            float* awrow = attnw + ((size_t)b * TLEN + t) * SLEN;
            const float* Vbase = QKV + (size_t)voff + (size_t)b * 768;
            float outv = 0.f;
#pragma unroll
            for (int i = 0; i < 32; i++) {
                float w = (a[i] > tau) ? (a[i] - tau) : 0.f;
                unsigned m = __ballot_sync(0xffffffffu, w > 0.f);
                if (w > 0.f) {
                    int s_me = (i >> 2) * 128 + lane * 4 + (i & 3);
                    atomicAdd(awrow + s_me, 0.125f * w);
                }
                while (m) {
                    int j = __ffs(m) - 1;
                    m &= m - 1;
                    float wj = __shfl_sync(0xffffffffu, w, j);
                    int s = (i >> 2) * 128 + j * 4 + (i & 3);
                    outv = fmaf(wj, Vbase[(size_t)s * 12288 + lane], outv);
                }
            }
            g_ctx[((size_t)t * BSZ + b) * EMB + h * HD + lane] = outv;
        }
    }
}

// ---------------- launcher ---------------------------------------------------
extern "C" void kernel_launch(void* const* d_in, const int* in_sizes, int n_in,
                              void* d_out, int out_size)
{
    const float* query = (const float*)d_in[0];
    const float* key   = (const float*)d_in[1];
    const float* value = (const float*)d_in[2];
    const float* Win   = (const float*)d_in[3];
    const float* bin   = (const float*)d_in[4];
    const float* Wout  = (const float*)d_in[5];
    const float* bout  = (const float*)d_in[6];

    float* outp  = (float*)d_out;                         // [1024,16,256]
    float* attnw = outp + (size_t)MROWS * EMB;            // [16,1024,1024]

    const int ATTN_SMEM = 32 * 1024 * (int)sizeof(float);
    cudaFuncSetAttribute(attn_kernel, cudaFuncAttributeMaxDynamicSharedMemorySize,
                         ATTN_SMEM);

    // 1) zero averaged attention-weights output (sparse atomics accumulate into it)
    zero_f4<<<2048, 256>>>((float4*)attnw, (int)((size_t)BSZ * TLEN * SLEN / 4));

    // 2) QKV projection (M=16384, N=768, K=256)
    gemm_k<0><<<dim3(768 / 64, MROWS / 128), 256>>>(query, key, value, Win, bin, nullptr);

    // 3) fused attention: scores + sparsemax + AV + avg attn weights
    attn_kernel<<<BH, 512, ATTN_SMEM>>>(attnw);

    // 4) output projection (M=16384, N=256, K=256)
    gemm_k<1><<<dim3(256 / 64, MROWS / 128), 256>>>(nullptr, nullptr, nullptr, Wout, bout, outp);
}